// round 6
// baseline (speedup 1.0000x reference)
#include <cuda_runtime.h>
#include <math.h>

// Problem constants
#define NBANDS   7
#define SCH      16
#define DCH      128
#define BATCH    32
#define TLEN     2048
#define KMAX     31
#define TT       64           // tokens per CTA
#define NTHREADS 256

__constant__ int c_KS[NBANDS] = {31, 21, 15, 11, 7, 5, 3};

// cat buffer [B, T, NB*64] = 32*2048*448 floats (~117 MB), device global (no alloc)
__device__ float g_cat[BATCH * TLEN * 448];

__device__ __forceinline__ float gelu_exact(float v) {
    return 0.5f * v * (1.0f + erff(v * 0.70710678118654752f));
}

// ---------------- Kernel 1: per-band conv + LN + LN + FFN + proj ----------------
// smem float offsets
#define K1_SX   0                    // x halo: 94*16 = 1504 (pad to 1536)
#define K1_SHL  1536                 // h after dec-LN: 64*128
#define K1_SZ   (K1_SHL + 8192)      // z (later band_out): 64*128
#define K1_SU   (K1_SZ + 8192)       // u: 64*256
#define K1_SW   (K1_SU + 16384)      // weight chunk: up to 128*128
#define K1_FLOATS (K1_SW + 16384)
#define K1_BYTES  (K1_FLOATS * 4)    // 202752 B

__global__ __launch_bounds__(NTHREADS, 1)
void band_kernel(const float* __restrict__ x,
                 const float* __restrict__ conv_w,
                 const float* __restrict__ conv_b,
                 const float* __restrict__ dec_g, const float* __restrict__ dec_b,
                 const float* __restrict__ n2_g,  const float* __restrict__ n2_b,
                 const float* __restrict__ ffn_w1, const float* __restrict__ ffn_b1,
                 const float* __restrict__ ffn_w2, const float* __restrict__ ffn_b2,
                 const float* __restrict__ proj_w, const float* __restrict__ proj_b)
{
    extern __shared__ float sm[];
    const int tid  = threadIdx.x;
    const int warp = tid >> 5, lane = tid & 31;
    const int n = blockIdx.z, b = blockIdx.y;
    const int t0 = blockIdx.x * TT;
    const int tokBase = warp * 8;      // 8 tokens per warp

    // ---- load x halo tile [t0-15, t0+64+14] x 16 channels ----
    for (int idx = tid; idx < 94 * 16; idx += NTHREADS) {
        int it = idx >> 4, s = idx & 15;
        int t = t0 - 15 + it;
        sm[K1_SX + idx] = (t >= 0 && t < TLEN) ? x[(b * TLEN + t) * 16 + s] : 0.0f;
    }

    // ---- conv over effective taps only (zero-padded taps skipped exactly) ----
    const int K = c_KS[n];
    const int off = (31 - K) >> 1;
    const int pairs = K * 16;          // (k,s) pairs

    float4 acc[8];
    #pragma unroll
    for (int tt = 0; tt < 8; tt++) acc[tt] = make_float4(0.f, 0.f, 0.f, 0.f);

    for (int c0 = 0; c0 < pairs; c0 += 128) {
        int cnt = min(128, pairs - c0);
        __syncthreads();
        for (int idx4 = tid; idx4 < cnt * 32; idx4 += NTHREADS) {
            int i = idx4 >> 5, d4 = (idx4 & 31) << 2;
            int p = c0 + i;
            int kk = off + (p >> 4), ss = p & 15;
            *(float4*)&sm[K1_SW + i * 128 + d4] =
                *(const float4*)&conv_w[(((n * 31 + kk) * 16 + ss) * 128) + d4];
        }
        __syncthreads();
        for (int i = 0; i < cnt; i++) {
            int p = c0 + i;
            float4 wv = *(float4*)&sm[K1_SW + i * 128 + (lane << 2)];
            int xb = K1_SX + (tokBase + off + (p >> 4)) * 16 + (p & 15);
            #pragma unroll
            for (int tt = 0; tt < 8; tt++) {
                float xv = sm[xb + tt * 16];
                acc[tt].x = fmaf(wv.x, xv, acc[tt].x);
                acc[tt].y = fmaf(wv.y, xv, acc[tt].y);
                acc[tt].z = fmaf(wv.z, xv, acc[tt].z);
                acc[tt].w = fmaf(wv.w, xv, acc[tt].w);
            }
        }
    }

    // ---- bias + dec-LN + n2-LN ----
    {
        float4 cb  = *(const float4*)&conv_b[n * 128 + lane * 4];
        float4 g1  = *(const float4*)&dec_g [n * 128 + lane * 4];
        float4 bb1 = *(const float4*)&dec_b [n * 128 + lane * 4];
        float4 g2  = *(const float4*)&n2_g  [n * 128 + lane * 4];
        float4 bb2 = *(const float4*)&n2_b  [n * 128 + lane * 4];
        #pragma unroll
        for (int tt = 0; tt < 8; tt++) {
            float4 a = acc[tt];
            a.x += cb.x; a.y += cb.y; a.z += cb.z; a.w += cb.w;
            // LN1
            float s1 = a.x + a.y + a.z + a.w;
            float s2 = fmaf(a.x, a.x, fmaf(a.y, a.y, fmaf(a.z, a.z, a.w * a.w)));
            #pragma unroll
            for (int o = 16; o; o >>= 1) {
                s1 += __shfl_xor_sync(0xffffffffu, s1, o);
                s2 += __shfl_xor_sync(0xffffffffu, s2, o);
            }
            float mean = s1 * 0.0078125f;
            float var  = s2 * 0.0078125f - mean * mean;
            float rs = rsqrtf(var + 1e-5f);
            float4 hl;
            hl.x = (a.x - mean) * rs * g1.x + bb1.x;
            hl.y = (a.y - mean) * rs * g1.y + bb1.y;
            hl.z = (a.z - mean) * rs * g1.z + bb1.z;
            hl.w = (a.w - mean) * rs * g1.w + bb1.w;
            // LN2 on hl
            float t1 = hl.x + hl.y + hl.z + hl.w;
            float t2 = fmaf(hl.x, hl.x, fmaf(hl.y, hl.y, fmaf(hl.z, hl.z, hl.w * hl.w)));
            #pragma unroll
            for (int o = 16; o; o >>= 1) {
                t1 += __shfl_xor_sync(0xffffffffu, t1, o);
                t2 += __shfl_xor_sync(0xffffffffu, t2, o);
            }
            float m2 = t1 * 0.0078125f;
            float v2 = t2 * 0.0078125f - m2 * m2;
            float rs2 = rsqrtf(v2 + 1e-5f);
            float4 z4;
            z4.x = (hl.x - m2) * rs2 * g2.x + bb2.x;
            z4.y = (hl.y - m2) * rs2 * g2.y + bb2.y;
            z4.z = (hl.z - m2) * rs2 * g2.z + bb2.z;
            z4.w = (hl.w - m2) * rs2 * g2.w + bb2.w;
            *(float4*)&sm[K1_SHL + (tokBase + tt) * 128 + lane * 4] = hl;
            *(float4*)&sm[K1_SZ  + (tokBase + tt) * 128 + lane * 4] = z4;
        }
    }

    // ---- FFN1: u = gelu(z @ W1 + b1), 256 outputs in 2 chunks of 128 ----
    for (int ec = 0; ec < 2; ec++) {
        __syncthreads();
        for (int idx4 = tid; idx4 < 128 * 32; idx4 += NTHREADS) {
            int d = idx4 >> 5, e4 = (idx4 & 31) << 2;
            *(float4*)&sm[K1_SW + d * 128 + e4] =
                *(const float4*)&ffn_w1[(n * 128 + d) * 256 + ec * 128 + e4];
        }
        __syncthreads();
        float4 ub = *(const float4*)&ffn_b1[n * 256 + ec * 128 + lane * 4];
        float4 u[8];
        #pragma unroll
        for (int tt = 0; tt < 8; tt++) u[tt] = ub;
        for (int d = 0; d < 128; d++) {
            float4 wv = *(float4*)&sm[K1_SW + d * 128 + (lane << 2)];
            #pragma unroll
            for (int tt = 0; tt < 8; tt++) {
                float zv = sm[K1_SZ + (tokBase + tt) * 128 + d];
                u[tt].x = fmaf(zv, wv.x, u[tt].x);
                u[tt].y = fmaf(zv, wv.y, u[tt].y);
                u[tt].z = fmaf(zv, wv.z, u[tt].z);
                u[tt].w = fmaf(zv, wv.w, u[tt].w);
            }
        }
        #pragma unroll
        for (int tt = 0; tt < 8; tt++) {
            float4 gv;
            gv.x = gelu_exact(u[tt].x); gv.y = gelu_exact(u[tt].y);
            gv.z = gelu_exact(u[tt].z); gv.w = gelu_exact(u[tt].w);
            *(float4*)&sm[K1_SU + (tokBase + tt) * 256 + ec * 128 + lane * 4] = gv;
        }
    }

    // ---- FFN2: band_out = h_ln + u @ W2 + b2 ----
    float4 bo[8];
    {
        float4 fb2 = *(const float4*)&ffn_b2[n * 128 + lane * 4];
        #pragma unroll
        for (int tt = 0; tt < 8; tt++) {
            float4 hl = *(float4*)&sm[K1_SHL + (tokBase + tt) * 128 + lane * 4];
            bo[tt].x = hl.x + fb2.x; bo[tt].y = hl.y + fb2.y;
            bo[tt].z = hl.z + fb2.z; bo[tt].w = hl.w + fb2.w;
        }
    }
    for (int ec = 0; ec < 2; ec++) {
        __syncthreads();
        for (int idx4 = tid; idx4 < 128 * 32; idx4 += NTHREADS) {
            int i = idx4 >> 5, d4 = (idx4 & 31) << 2;
            *(float4*)&sm[K1_SW + i * 128 + d4] =
                *(const float4*)&ffn_w2[(n * 256 + ec * 128 + i) * 128 + d4];
        }
        __syncthreads();
        for (int i = 0; i < 128; i++) {
            float4 wv = *(float4*)&sm[K1_SW + i * 128 + (lane << 2)];
            #pragma unroll
            for (int tt = 0; tt < 8; tt++) {
                float uv = sm[K1_SU + (tokBase + tt) * 256 + ec * 128 + i];
                bo[tt].x = fmaf(uv, wv.x, bo[tt].x);
                bo[tt].y = fmaf(uv, wv.y, bo[tt].y);
                bo[tt].z = fmaf(uv, wv.z, bo[tt].z);
                bo[tt].w = fmaf(uv, wv.w, bo[tt].w);
            }
        }
    }

    // ---- proj: p = band_out @ proj_w + proj_b -> g_cat ----
    #pragma unroll
    for (int tt = 0; tt < 8; tt++)
        *(float4*)&sm[K1_SZ + (tokBase + tt) * 128 + lane * 4] = bo[tt];   // reuse SZ
    __syncthreads();
    for (int idx4 = tid; idx4 < 2048; idx4 += NTHREADS)                    // 128x64 weights
        *(float4*)&sm[K1_SW + idx4 * 4] = *(const float4*)&proj_w[n * 8192 + idx4 * 4];
    __syncthreads();
    {
        float2 pb = *(const float2*)&proj_b[n * 64 + lane * 2];
        float2 pr[8];
        #pragma unroll
        for (int tt = 0; tt < 8; tt++) pr[tt] = pb;
        for (int d = 0; d < 128; d++) {
            float2 wv = *(float2*)&sm[K1_SW + d * 64 + (lane << 1)];
            #pragma unroll
            for (int tt = 0; tt < 8; tt++) {
                float bv = sm[K1_SZ + (tokBase + tt) * 128 + d];
                pr[tt].x = fmaf(bv, wv.x, pr[tt].x);
                pr[tt].y = fmaf(bv, wv.y, pr[tt].y);
            }
        }
        #pragma unroll
        for (int tt = 0; tt < 8; tt++) {
            int t = t0 + tokBase + tt;
            *(float2*)&g_cat[(b * TLEN + t) * 448 + n * 64 + lane * 2] = pr[tt];
        }
    }
}

// ---------------- Kernel 2: mix MLP over the 448-wide cat ----------------
#define K2_CAT 0                 // 64*448
#define K2_SM  28672             // 64*128
#define K2_SW  (K2_SM + 8192)    // 128*128 chunk
#define K2_SW2 (K2_SW + 16384)   // 128*16
#define K2_FLOATS (K2_SW2 + 2048)
#define K2_BYTES  (K2_FLOATS * 4)  // 221184 B

__global__ __launch_bounds__(NTHREADS, 1)
void mix_kernel(const float* __restrict__ mix_w1, const float* __restrict__ mix_b1,
                const float* __restrict__ mix_w2, const float* __restrict__ mix_b2,
                float* __restrict__ out)
{
    extern __shared__ float sm[];
    const int tid = threadIdx.x, warp = tid >> 5, lane = tid & 31;
    const int g0 = blockIdx.x * TT;
    const int tokBase = warp * 8;

    for (int idx4 = tid; idx4 < 64 * 112; idx4 += NTHREADS)
        *(float4*)&sm[K2_CAT + idx4 * 4] = *(const float4*)&g_cat[(size_t)g0 * 448 + idx4 * 4];

    float4 m4[8];
    {
        float4 mb = *(const float4*)&mix_b1[lane * 4];
        #pragma unroll
        for (int tt = 0; tt < 8; tt++) m4[tt] = mb;
    }
    for (int dc = 0; dc < 448; dc += 128) {
        int cnt = min(128, 448 - dc);
        __syncthreads();
        for (int idx4 = tid; idx4 < cnt * 32; idx4 += NTHREADS) {
            int i = idx4 >> 5, d4 = (idx4 & 31) << 2;
            *(float4*)&sm[K2_SW + i * 128 + d4] = *(const float4*)&mix_w1[(dc + i) * 128 + d4];
        }
        __syncthreads();
        for (int i = 0; i < cnt; i++) {
            float4 wv = *(float4*)&sm[K2_SW + i * 128 + (lane << 2)];
            #pragma unroll
            for (int tt = 0; tt < 8; tt++) {
                float cv = sm[K2_CAT + (tokBase + tt) * 448 + dc + i];
                m4[tt].x = fmaf(cv, wv.x, m4[tt].x);
                m4[tt].y = fmaf(cv, wv.y, m4[tt].y);
                m4[tt].z = fmaf(cv, wv.z, m4[tt].z);
                m4[tt].w = fmaf(cv, wv.w, m4[tt].w);
            }
        }
    }
    #pragma unroll
    for (int tt = 0; tt < 8; tt++) {
        float4 gv;
        gv.x = gelu_exact(m4[tt].x); gv.y = gelu_exact(m4[tt].y);
        gv.z = gelu_exact(m4[tt].z); gv.w = gelu_exact(m4[tt].w);
        *(float4*)&sm[K2_SM + (tokBase + tt) * 128 + lane * 4] = gv;
    }
    __syncthreads();
    for (int idx4 = tid; idx4 < 512; idx4 += NTHREADS)
        *(float4*)&sm[K2_SW2 + idx4 * 4] = *(const float4*)&mix_w2[idx4 * 4];
    __syncthreads();

    // out = m @ W2 + b2 : lane = (half, j), split-K over d with shfl reduce
    {
        const int j = lane & 15, half = lane >> 4;
        float o[8];
        #pragma unroll
        for (int tt = 0; tt < 8; tt++) o[tt] = 0.f;
        for (int dd = 0; dd < 64; dd++) {
            int d = half * 64 + dd;
            float w = sm[K2_SW2 + d * 16 + j];
            #pragma unroll
            for (int tt = 0; tt < 8; tt++) {
                float mv = sm[K2_SM + (tokBase + tt) * 128 + d];
                o[tt] = fmaf(mv, w, o[tt]);
            }
        }
        float bj = mix_b2[j];
        #pragma unroll
        for (int tt = 0; tt < 8; tt++) {
            o[tt] += __shfl_xor_sync(0xffffffffu, o[tt], 16);
            if (half == 0)
                out[(g0 + tokBase + tt) * 16 + j] = o[tt] + bj;
        }
    }
}

// ---------------- launch ----------------
extern "C" void kernel_launch(void* const* d_in, const int* in_sizes, int n_in,
                              void* d_out, int out_size)
{
    const float* x      = (const float*)d_in[0];
    const float* conv_w = (const float*)d_in[1];
    const float* conv_b = (const float*)d_in[2];
    const float* dec_g  = (const float*)d_in[3];
    const float* dec_b  = (const float*)d_in[4];
    const float* n2_g   = (const float*)d_in[5];
    const float* n2_b   = (const float*)d_in[6];
    const float* ffn_w1 = (const float*)d_in[7];
    const float* ffn_b1 = (const float*)d_in[8];
    const float* ffn_w2 = (const float*)d_in[9];
    const float* ffn_b2 = (const float*)d_in[10];
    const float* proj_w = (const float*)d_in[11];
    const float* proj_b = (const float*)d_in[12];
    const float* mix_w1 = (const float*)d_in[13];
    const float* mix_b1 = (const float*)d_in[14];
    const float* mix_w2 = (const float*)d_in[15];
    const float* mix_b2 = (const float*)d_in[16];
    float* out = (float*)d_out;

    cudaFuncSetAttribute(band_kernel, cudaFuncAttributeMaxDynamicSharedMemorySize, K1_BYTES);
    cudaFuncSetAttribute(mix_kernel,  cudaFuncAttributeMaxDynamicSharedMemorySize, K2_BYTES);

    dim3 grid1(TLEN / TT, BATCH, NBANDS);
    band_kernel<<<grid1, NTHREADS, K1_BYTES>>>(x, conv_w, conv_b, dec_g, dec_b,
                                               n2_g, n2_b, ffn_w1, ffn_b1,
                                               ffn_w2, ffn_b2, proj_w, proj_b);
    mix_kernel<<<(BATCH * TLEN) / TT, NTHREADS, K2_BYTES>>>(mix_w1, mix_b1,
                                                            mix_w2, mix_b2, out);
}

// round 7
// speedup vs baseline: 1.1807x; 1.1807x over previous
#include <cuda_runtime.h>
#include <math.h>

// Problem constants
#define NBANDS   7
#define BATCH    32
#define TLEN     2048
#define TT       64
#define NTHREADS 256

__constant__ int c_KS[7]    = {31, 21, 15, 11, 7, 5, 3};
__constant__ int c_off[7]   = {0, 5, 8, 10, 12, 13, 14};
__constant__ int c_pairs[7] = {496, 336, 240, 176, 112, 80, 48};
__constant__ int c_convElemStart[8] = {0, 63488, 106496, 137216, 159744, 174080, 184320, 190464};
__constant__ int c_convPackBase[7]  = {0, 126976, 212992, 274432, 319488, 348160, 368640};

// device-global scratch (no allocations allowed)
__device__ __align__(16) float g_cat[BATCH * TLEN * 448];      // ~117 MB
__device__ __align__(16) float g_convp[380928];                // packed tf32 hi/lo fragments
__device__ __align__(16) float g_ffn1p[7 * 65536];
__device__ __align__(16) float g_ffn2p[7 * 65536];
__device__ __align__(16) float g_projp[7 * 16384];
__device__ __align__(16) float g_mixp[114688];

__device__ __forceinline__ unsigned tf32u(float x) {
    unsigned r; asm("cvt.rna.tf32.f32 %0, %1;" : "=r"(r) : "f"(x)); return r;
}
__device__ __forceinline__ float gelu_exact(float v) {
    return 0.5f * v * (1.0f + erff(v * 0.70710678118654752f));
}
__device__ __forceinline__ void mma8(float4& d, unsigned a0, unsigned a1, unsigned a2, unsigned a3,
                                     unsigned b0, unsigned b1) {
    asm volatile("mma.sync.aligned.m16n8k8.row.col.f32.tf32.tf32.f32 "
        "{%0,%1,%2,%3}, {%4,%5,%6,%7}, {%8,%9}, {%0,%1,%2,%3};"
        : "+f"(d.x), "+f"(d.y), "+f"(d.z), "+f"(d.w)
        : "r"(a0), "r"(a1), "r"(a2), "r"(a3), "r"(b0), "r"(b1));
}

// fragment offset within a packed [KT*8 x (ntiles*8)] block:
// float4 slot index = (jt*KT + kt)*32 + lane, components: {b0_hi, b1_hi, b0_lo, b1_lo}
__device__ __forceinline__ int frag_off(int kk, int dd, int KT) {
    int k8 = kk & 7;
    return ((((dd >> 3) * KT + (kk >> 3)) * 32 + (dd & 7) * 4 + (k8 & 3)) * 4) + (k8 >> 2);
}

__device__ __forceinline__ void copy_f4(float* dst, const float* src, int nf) {
    for (int i = threadIdx.x << 2; i < nf; i += NTHREADS << 2)
        *(float4*)(dst + i) = *(const float4*)(src + i);
}

// ---- generic warp-level split-tf32 MMA: D[JT] += A[16 x KT*8] * B ----
// A: plain row-major smem (stride sA, col offset k0). Bp: packed fragments (pre-offset per warp).
template<int JT>
__device__ __forceinline__ void warp_mma(const float* __restrict__ As, int sA, int mbase, int k0,
                                         int KT, const float* __restrict__ Bp, float4* D, int lane)
{
    const int g = lane >> 2, t = lane & 3;
    const float* a0p = As + (mbase + g) * sA + k0 + t;
    const float* a1p = a0p + 8 * sA;
    const uint4* bp = (const uint4*)Bp + lane;
    for (int kt = 0; kt < KT; kt++) {
        float a0 = a0p[0], a2 = a0p[4];
        float a1 = a1p[0], a3 = a1p[4];
        a0p += 8; a1p += 8;
        unsigned h0 = tf32u(a0), h1 = tf32u(a1), h2 = tf32u(a2), h3 = tf32u(a3);
        unsigned l0 = tf32u(a0 - __uint_as_float(h0));
        unsigned l1 = tf32u(a1 - __uint_as_float(h1));
        unsigned l2 = tf32u(a2 - __uint_as_float(h2));
        unsigned l3 = tf32u(a3 - __uint_as_float(h3));
        #pragma unroll
        for (int j = 0; j < JT; j++) {
            uint4 B = bp[(j * KT + kt) * 32];
            mma8(D[j], h0, h1, h2, h3, B.x, B.y);   // hi * hi
            mma8(D[j], h0, h1, h2, h3, B.z, B.w);   // hi * lo
            mma8(D[j], l0, l1, l2, l3, B.x, B.y);   // lo * hi
        }
    }
}

// ---------------- weight pre-pack: tf32 hi/lo fragment layout ----------------
__global__ void pack_weights(const float* __restrict__ conv_w, const float* __restrict__ ffn_w1,
                             const float* __restrict__ ffn_w2, const float* __restrict__ proj_w,
                             const float* __restrict__ mix_w1)
{
    const int TOT = 763904;
    for (int i = blockIdx.x * blockDim.x + threadIdx.x; i < TOT; i += gridDim.x * blockDim.x) {
        float w; float* dst;
        if (i < 190464) {                      // conv
            int n = 0;
            while (i >= c_convElemStart[n + 1]) n++;
            int e = i - c_convElemStart[n];
            int p = e >> 7, dd = e & 127;
            int c0 = p & ~63;
            int KT = min(64, c_pairs[n] - c0) >> 3;
            w = conv_w[((n * 31 + c_off[n] + (p >> 4)) * 16 + (p & 15)) * 128 + dd];
            dst = g_convp + c_convPackBase[n] + c0 * 256 + frag_off(p - c0, dd, KT);
        } else if (i < 419840) {               // ffn_w1 [7][128][256]
            int e = i - 190464;
            int n = e >> 15, r = e & 32767;
            int kk = r >> 8, dd = r & 255;
            w = ffn_w1[(n * 128 + kk) * 256 + dd];
            dst = g_ffn1p + n * 65536 + (dd >> 6) * 16384 + frag_off(kk, dd & 63, 16);
        } else if (i < 649216) {               // ffn_w2 [7][256][128]
            int e = i - 419840;
            int n = e >> 15, r = e & 32767;
            int kk = r >> 7, dd = r & 127;
            w = ffn_w2[(n * 256 + kk) * 128 + dd];
            dst = g_ffn2p + n * 65536 + ((dd >> 6) * 2 + (kk >> 7)) * 16384 + frag_off(kk & 127, dd & 63, 16);
        } else if (i < 706560) {               // proj_w [7][128][64]
            int e = i - 649216;
            int n = e >> 13, r = e & 8191;
            int kk = r >> 6, dd = r & 63;
            w = proj_w[(n * 128 + kk) * 64 + dd];
            dst = g_projp + n * 16384 + frag_off(kk, dd, 16);
        } else {                               // mix_w1 [448][128]
            int e = i - 706560;
            int kk = e >> 7, dd = e & 127;
            int kp = kk >> 7, ec = dd >> 6;
            int KT = (kp == 3) ? 8 : 16;
            int base = (kp < 3) ? kp * 32768 + ec * 16384 : 98304 + ec * 8192;
            w = mix_w1[kk * 128 + dd];
            dst = g_mixp + base + frag_off(kk & 127, dd & 63, KT);
        }
        unsigned hb = tf32u(w);
        float hf = __uint_as_float(hb);
        unsigned lb = tf32u(w - hf);
        dst[0] = hf;
        dst[2] = __uint_as_float(lb);
    }
}

// ---------------- Kernel 1: per-band conv + LN + LN + FFN + proj ----------------
// smem float offsets (padded strides: 132 / 260, all == 4 mod 32 for conflict-free frags)
#define SXH 0                       // halo 94*16 -> 1536
#define SHL 1536                    // h_ln: 64*132
#define SZ  (SHL + 8448)            // raw conv -> z -> band_out: 64*132
#define SU  (SZ + 8448)             // u: 64*260
#define SBP (SU + 16640)            // packed weight chunk: 16384
#define K1F (SBP + 16384)           // 51456 floats
#define K1B (K1F * 4)               // 205824 B

__global__ __launch_bounds__(NTHREADS, 1)
void band_kernel(const float* __restrict__ x,
                 const float* __restrict__ conv_b,
                 const float* __restrict__ dec_g, const float* __restrict__ dec_b,
                 const float* __restrict__ n2_g,  const float* __restrict__ n2_b,
                 const float* __restrict__ ffn_b1, const float* __restrict__ ffn_b2,
                 const float* __restrict__ proj_b)
{
    extern __shared__ float sm[];
    const int tid = threadIdx.x, warp = tid >> 5, lane = tid & 31;
    const int n = blockIdx.z, b = blockIdx.y, t0 = blockIdx.x * TT;
    const int mb = (warp >> 1) << 4;     // row tile base (16 tokens)
    const int nh = warp & 1;             // column half
    const int g = lane >> 2, t = lane & 3;

    // halo load [t0-15, t0+78] x 16
    for (int idx = tid; idx < 94 * 16; idx += NTHREADS) {
        int it = idx >> 4, s = idx & 15;
        int tt = t0 - 15 + it;
        sm[SXH + idx] = (tt >= 0 && tt < TLEN) ? x[(b * TLEN + tt) * 16 + s] : 0.0f;
    }

    // ---- conv: im2col GEMM [64 x pairs] @ [pairs x 128] ----
    const int pairs = c_pairs[n], off = c_off[n];
    const float* cbase = g_convp + c_convPackBase[n];
    float4 D8[8];
    #pragma unroll
    for (int j = 0; j < 8; j++) D8[j] = make_float4(0.f, 0.f, 0.f, 0.f);
    for (int c0 = 0; c0 < pairs; c0 += 64) {
        int KT = min(64, pairs - c0) >> 3;
        __syncthreads();
        copy_f4(sm + SBP, cbase + c0 * 256, KT * 2048);
        __syncthreads();
        warp_mma<8>(sm + SXH + off * 16, 16, mb, c0, KT, sm + SBP + nh * KT * 1024, D8, lane);
    }
    #pragma unroll
    for (int j = 0; j < 8; j++) {
        int col = nh * 64 + j * 8 + 2 * t;
        *(float2*)&sm[SZ + (mb + g) * 132 + col]     = make_float2(D8[j].x, D8[j].y);
        *(float2*)&sm[SZ + (mb + g + 8) * 132 + col] = make_float2(D8[j].z, D8[j].w);
    }
    __syncthreads();

    // ---- bias + dec-LN + n2-LN (fp32 exact) ----
    {
        float4 cb4 = *(const float4*)&conv_b[n * 128 + lane * 4];
        float4 g1  = *(const float4*)&dec_g [n * 128 + lane * 4];
        float4 bb1 = *(const float4*)&dec_b [n * 128 + lane * 4];
        float4 g2  = *(const float4*)&n2_g  [n * 128 + lane * 4];
        float4 bb2 = *(const float4*)&n2_b  [n * 128 + lane * 4];
        for (int tt = 0; tt < 8; tt++) {
            int row = warp * 8 + tt;
            float4 a = *(float4*)&sm[SZ + row * 132 + lane * 4];
            a.x += cb4.x; a.y += cb4.y; a.z += cb4.z; a.w += cb4.w;
            float s1 = a.x + a.y + a.z + a.w;
            float s2 = fmaf(a.x, a.x, fmaf(a.y, a.y, fmaf(a.z, a.z, a.w * a.w)));
            #pragma unroll
            for (int o = 16; o; o >>= 1) {
                s1 += __shfl_xor_sync(0xffffffffu, s1, o);
                s2 += __shfl_xor_sync(0xffffffffu, s2, o);
            }
            float mean = s1 * 0.0078125f;
            float var  = s2 * 0.0078125f - mean * mean;
            float rs = rsqrtf(var + 1e-5f);
            float4 hl;
            hl.x = (a.x - mean) * rs * g1.x + bb1.x;
            hl.y = (a.y - mean) * rs * g1.y + bb1.y;
            hl.z = (a.z - mean) * rs * g1.z + bb1.z;
            hl.w = (a.w - mean) * rs * g1.w + bb1.w;
            float t1 = hl.x + hl.y + hl.z + hl.w;
            float t2 = fmaf(hl.x, hl.x, fmaf(hl.y, hl.y, fmaf(hl.z, hl.z, hl.w * hl.w)));
            #pragma unroll
            for (int o = 16; o; o >>= 1) {
                t1 += __shfl_xor_sync(0xffffffffu, t1, o);
                t2 += __shfl_xor_sync(0xffffffffu, t2, o);
            }
            float m2 = t1 * 0.0078125f;
            float v2 = t2 * 0.0078125f - m2 * m2;
            float rs2 = rsqrtf(v2 + 1e-5f);
            float4 z4;
            z4.x = (hl.x - m2) * rs2 * g2.x + bb2.x;
            z4.y = (hl.y - m2) * rs2 * g2.y + bb2.y;
            z4.z = (hl.z - m2) * rs2 * g2.z + bb2.z;
            z4.w = (hl.w - m2) * rs2 * g2.w + bb2.w;
            *(float4*)&sm[SHL + row * 132 + lane * 4] = hl;
            *(float4*)&sm[SZ  + row * 132 + lane * 4] = z4;
        }
    }

    // ---- FFN1: u = gelu(z @ W1 + b1), 4 chunks of 64 cols ----
    for (int ec = 0; ec < 4; ec++) {
        __syncthreads();
        copy_f4(sm + SBP, g_ffn1p + n * 65536 + ec * 16384, 16384);
        __syncthreads();
        float4 Du[4];
        int colb = ec * 64 + nh * 32;
        #pragma unroll
        for (int j = 0; j < 4; j++) {
            float2 bb = *(const float2*)&ffn_b1[n * 256 + colb + j * 8 + 2 * t];
            Du[j] = make_float4(bb.x, bb.y, bb.x, bb.y);
        }
        warp_mma<4>(sm + SZ, 132, mb, 0, 16, sm + SBP + nh * 8192, Du, lane);
        #pragma unroll
        for (int j = 0; j < 4; j++) {
            int col = colb + j * 8 + 2 * t;
            *(float2*)&sm[SU + (mb + g) * 260 + col] =
                make_float2(gelu_exact(Du[j].x), gelu_exact(Du[j].y));
            *(float2*)&sm[SU + (mb + g + 8) * 260 + col] =
                make_float2(gelu_exact(Du[j].z), gelu_exact(Du[j].w));
        }
    }

    // ---- FFN2: band_out = h_ln + u @ W2 + b2 -> SZ ----
    for (int ec2 = 0; ec2 < 2; ec2++) {
        float4 Db[4];
        int colb = ec2 * 64 + nh * 32;
        #pragma unroll
        for (int j = 0; j < 4; j++) {
            int col = colb + j * 8 + 2 * t;
            float2 bb = *(const float2*)&ffn_b2[n * 128 + col];
            Db[j].x = sm[SHL + (mb + g) * 132 + col]       + bb.x;
            Db[j].y = sm[SHL + (mb + g) * 132 + col + 1]   + bb.y;
            Db[j].z = sm[SHL + (mb + g + 8) * 132 + col]   + bb.x;
            Db[j].w = sm[SHL + (mb + g + 8) * 132 + col + 1] + bb.y;
        }
        for (int kp = 0; kp < 2; kp++) {
            __syncthreads();
            copy_f4(sm + SBP, g_ffn2p + n * 65536 + (ec2 * 2 + kp) * 16384, 16384);
            __syncthreads();
            warp_mma<4>(sm + SU, 260, mb, kp * 128, 16, sm + SBP + nh * 8192, Db, lane);
        }
        #pragma unroll
        for (int j = 0; j < 4; j++) {
            int col = colb + j * 8 + 2 * t;
            *(float2*)&sm[SZ + (mb + g) * 132 + col]     = make_float2(Db[j].x, Db[j].y);
            *(float2*)&sm[SZ + (mb + g + 8) * 132 + col] = make_float2(Db[j].z, Db[j].w);
        }
    }

    // ---- proj -> g_cat ----
    __syncthreads();
    copy_f4(sm + SBP, g_projp + n * 16384, 16384);
    __syncthreads();
    {
        float4 Dp[4];
        int colb = nh * 32;
        #pragma unroll
        for (int j = 0; j < 4; j++) {
            float2 pb = *(const float2*)&proj_b[n * 64 + colb + j * 8 + 2 * t];
            Dp[j] = make_float4(pb.x, pb.y, pb.x, pb.y);
        }
        warp_mma<4>(sm + SZ, 132, mb, 0, 16, sm + SBP + nh * 8192, Dp, lane);
        #pragma unroll
        for (int j = 0; j < 4; j++) {
            int col = colb + j * 8 + 2 * t;
            int r1 = t0 + mb + g, r2 = r1 + 8;
            *(float2*)&g_cat[(b * TLEN + r1) * 448 + n * 64 + col] = make_float2(Dp[j].x, Dp[j].y);
            *(float2*)&g_cat[(b * TLEN + r2) * 448 + n * 64 + col] = make_float2(Dp[j].z, Dp[j].w);
        }
    }
}

// ---------------- Kernel 2: mix MLP ----------------
#define SCAT 0                        // 64*452
#define SM2  28928                    // 64*132
#define SBP2 (SM2 + 8448)             // 16384
#define SW2  (SBP2 + 16384)           // 2048
#define K2F  (SW2 + 2048)             // 55808 floats
#define K2B  (K2F * 4)                // 223232 B

__global__ __launch_bounds__(NTHREADS, 1)
void mix_kernel(const float* __restrict__ mix_b1, const float* __restrict__ mix_w2,
                const float* __restrict__ mix_b2, float* __restrict__ out)
{
    extern __shared__ float sm[];
    const int tid = threadIdx.x, warp = tid >> 5, lane = tid & 31;
    const int g0 = blockIdx.x * TT;
    const int mb = (warp >> 1) << 4;
    const int nh = warp & 1;
    const int g = lane >> 2, t = lane & 3;

    for (int idx = tid; idx < 64 * 112; idx += NTHREADS) {
        int r = idx / 112, c = idx - r * 112;
        *(float4*)&sm[SCAT + r * 452 + c * 4] = *(const float4*)&g_cat[(size_t)(g0 + r) * 448 + c * 4];
    }

    for (int ec = 0; ec < 2; ec++) {
        float4 Dm[4];
        int colb = ec * 64 + nh * 32;
        #pragma unroll
        for (int j = 0; j < 4; j++) {
            float2 bb = *(const float2*)&mix_b1[colb + j * 8 + 2 * t];
            Dm[j] = make_float4(bb.x, bb.y, bb.x, bb.y);
        }
        for (int kp = 0; kp < 4; kp++) {
            int KT = (kp == 3) ? 8 : 16;
            int base = (kp < 3) ? kp * 32768 + ec * 16384 : 98304 + ec * 8192;
            __syncthreads();
            copy_f4(sm + SBP2, g_mixp + base, KT * 1024);
            __syncthreads();
            warp_mma<4>(sm + SCAT, 452, mb, kp * 128, KT, sm + SBP2 + nh * KT * 512, Dm, lane);
        }
        #pragma unroll
        for (int j = 0; j < 4; j++) {
            int col = colb + j * 8 + 2 * t;
            *(float2*)&sm[SM2 + (mb + g) * 132 + col] =
                make_float2(gelu_exact(Dm[j].x), gelu_exact(Dm[j].y));
            *(float2*)&sm[SM2 + (mb + g + 8) * 132 + col] =
                make_float2(gelu_exact(Dm[j].z), gelu_exact(Dm[j].w));
        }
    }
    __syncthreads();
    for (int i4 = tid; i4 < 512; i4 += NTHREADS)
        *(float4*)&sm[SW2 + i4 * 4] = *(const float4*)&mix_w2[i4 * 4];
    __syncthreads();

    // final 128->16 GEMM in exact fp32 (tiny)
    {
        const int tokBase = warp * 8;
        const int j = lane & 15, half = lane >> 4;
        float o[8];
        #pragma unroll
        for (int tt = 0; tt < 8; tt++) o[tt] = 0.f;
        for (int dd = 0; dd < 64; dd++) {
            int d = half * 64 + dd;
            float w = sm[SW2 + d * 16 + j];
            #pragma unroll
            for (int tt = 0; tt < 8; tt++) {
                float mv = sm[SM2 + (tokBase + tt) * 132 + d];
                o[tt] = fmaf(mv, w, o[tt]);
            }
        }
        float bj = mix_b2[j];
        #pragma unroll
        for (int tt = 0; tt < 8; tt++) {
            o[tt] += __shfl_xor_sync(0xffffffffu, o[tt], 16);
            if (half == 0)
                out[(g0 + tokBase + tt) * 16 + j] = o[tt] + bj;
        }
    }
}

// ---------------- launch ----------------
extern "C" void kernel_launch(void* const* d_in, const int* in_sizes, int n_in,
                              void* d_out, int out_size)
{
    const float* x      = (const float*)d_in[0];
    const float* conv_w = (const float*)d_in[1];
    const float* conv_b = (const float*)d_in[2];
    const float* dec_g  = (const float*)d_in[3];
    const float* dec_b  = (const float*)d_in[4];
    const float* n2_g   = (const float*)d_in[5];
    const float* n2_b   = (const float*)d_in[6];
    const float* ffn_w1 = (const float*)d_in[7];
    const float* ffn_b1 = (const float*)d_in[8];
    const float* ffn_w2 = (const float*)d_in[9];
    const float* ffn_b2 = (const float*)d_in[10];
    const float* proj_w = (const float*)d_in[11];
    const float* proj_b = (const float*)d_in[12];
    const float* mix_w1 = (const float*)d_in[13];
    const float* mix_b1 = (const float*)d_in[14];
    const float* mix_w2 = (const float*)d_in[15];
    const float* mix_b2 = (const float*)d_in[16];
    float* out = (float*)d_out;

    cudaFuncSetAttribute(band_kernel, cudaFuncAttributeMaxDynamicSharedMemorySize, K1B);
    cudaFuncSetAttribute(mix_kernel,  cudaFuncAttributeMaxDynamicSharedMemorySize, K2B);

    pack_weights<<<1024, NTHREADS>>>(conv_w, ffn_w1, ffn_w2, proj_w, mix_w1);

    dim3 grid1(TLEN / TT, BATCH, NBANDS);
    band_kernel<<<grid1, NTHREADS, K1B>>>(x, conv_b, dec_g, dec_b, n2_g, n2_b,
                                          ffn_b1, ffn_b2, proj_b);
    mix_kernel<<<(BATCH * TLEN) / TT, NTHREADS, K2B>>>(mix_b1, mix_w2, mix_b2, out);
}

// round 14
// speedup vs baseline: 2.2126x; 1.8739x over previous
#include <cuda_runtime.h>
#include <math.h>

#define NBANDS   7
#define BATCH    32
#define TLEN     2048
#define TT       64
#define NTHREADS 256

__constant__ int c_KS[7]  = {31, 21, 15, 11, 7, 5, 3};
__constant__ int c_off[7] = {0, 5, 8, 10, 12, 13, 14};
__constant__ int c_cb[7]  = {0, 15872, 26624, 34304, 39936, 43520, 46080};   // conv bases (uint4)
__constant__ int c_convElemStart[8] = {0, 63488, 106496, 137216, 159744, 174080, 184320, 190464};

#define F1B 47616
#define F2B 104960
#define PJB 162304
#define MXB 176640
#define WPU4 190976

// device-global scratch (no allocations allowed)
__device__ __align__(16) uint4 g_wp[WPU4];                 // packed bf16 hi/lo weight fragments (~3MB)
__device__ __align__(16) uint2 g_cat[BATCH * TLEN * 224];  // cat as split bf16 pairs (~117MB)

__device__ __forceinline__ float gelu_exact(float v) {
    return 0.5f * v * (1.0f + erff(v * 0.70710678118654752f));
}
// split two fp32 into {hi bf16x2, lo bf16x2}; lower 16 bits hold e0
__device__ __forceinline__ uint2 split2(float e0, float e1) {
    unsigned hi; asm("cvt.rn.bf16x2.f32 %0, %1, %2;" : "=r"(hi) : "f"(e1), "f"(e0));
    float f0 = __uint_as_float(hi << 16);
    float f1 = __uint_as_float(hi & 0xffff0000u);
    unsigned lo; asm("cvt.rn.bf16x2.f32 %0, %1, %2;" : "=r"(lo) : "f"(e1 - f1), "f"(e0 - f0));
    return make_uint2(hi, lo);
}
__device__ __forceinline__ void mma16(float4& d, unsigned a0, unsigned a1, unsigned a2, unsigned a3,
                                      unsigned b0, unsigned b1) {
    asm volatile("mma.sync.aligned.m16n8k16.row.col.f32.bf16.bf16.f32 "
        "{%0,%1,%2,%3}, {%4,%5,%6,%7}, {%8,%9}, {%0,%1,%2,%3};"
        : "+f"(d.x), "+f"(d.y), "+f"(d.z), "+f"(d.w)
        : "r"(a0), "r"(a1), "r"(a2), "r"(a3), "r"(b0), "r"(b1));
}
__device__ __forceinline__ void cp_chunk(uint4* dst, const uint4* src, int n_u4) {
    unsigned sb = (unsigned)__cvta_generic_to_shared(dst);
    for (int i = threadIdx.x; i < n_u4; i += NTHREADS)
        asm volatile("cp.async.cg.shared.global [%0], [%1], 16;"
                     :: "r"(sb + i * 16), "l"(src + i));
    asm volatile("cp.async.commit_group;" ::: "memory");
}

__device__ __forceinline__ int2 band_chunk(int n, int idx, int ncc, int taps) {
    if (idx < ncc) {
        int KTc = min(4, taps - idx * 4);
        return make_int2(c_cb[n] + idx * 2048, KTc * 512);
    }
    int r = idx - ncc;
    if (r < 4) return make_int2(F1B + n * 8192 + r * 2048, 2048);
    if (r < 8) return make_int2(F2B + n * 8192 + (r - 4) * 2048, 2048);
    return make_int2(PJB + n * 2048, 2048);
}

// warp MMA: D[4] += A(pairs) * B(packed frags), A k-advance along columns
template<int KTC>
__device__ __forceinline__ void wmma4(const uint2* A0, const uint2* A1, const uint4* bp, float4* D) {
    #pragma unroll
    for (int kt = 0; kt < KTC; kt++) {
        uint2 P0 = A0[kt * 8], P2 = A0[kt * 8 + 4];
        uint2 P1 = A1[kt * 8], P3 = A1[kt * 8 + 4];
        #pragma unroll
        for (int j = 0; j < 4; j++) {
            uint4 Bv = bp[(j * KTC + kt) * 32];
            mma16(D[j], P0.x, P1.x, P2.x, P3.x, Bv.x, Bv.y);
            mma16(D[j], P0.x, P1.x, P2.x, P3.x, Bv.z, Bv.w);
            mma16(D[j], P0.y, P1.y, P2.y, P3.y, Bv.x, Bv.y);
        }
    }
}

// ---------------- weight pre-pack: bf16 hi/lo fragment layout ----------------
__global__ void pack_weights(const float* __restrict__ conv_w, const float* __restrict__ ffn_w1,
                             const float* __restrict__ ffn_w2, const float* __restrict__ proj_w,
                             const float* __restrict__ mix_w1)
{
    unsigned short* wp = (unsigned short*)g_wp;
    const int TOT = 763904;
    for (int i = blockIdx.x * blockDim.x + threadIdx.x; i < TOT; i += gridDim.x * blockDim.x) {
        float w; int base, jt, kt, KTc, n8, tq, kk16;
        if (i < 190464) {                       // conv
            int n = 0;
            while (i >= c_convElemStart[n + 1]) n++;
            int e = i - c_convElemStart[n];
            int p = e >> 7, dd = e & 127;
            int tap = p >> 4; kk16 = p & 15;
            int c = tap >> 2; kt = tap & 3;
            KTc = min(4, c_KS[n] - c * 4);
            jt = dd >> 3; n8 = dd & 7;
            base = c_cb[n] + c * 2048;
            w = conv_w[((n * 31 + c_off[n] + tap) * 16 + kk16) * 128 + dd];
        } else if (i < 419840) {                // ffn_w1 [7][128][256]
            int e = i - 190464;
            int n = e >> 15, r = e & 32767;
            int kk = r >> 8, dd = r & 255;
            base = F1B + n * 8192 + (dd >> 6) * 2048; KTc = 8;
            kt = kk >> 4; kk16 = kk & 15;
            int nl = dd & 63; jt = nl >> 3; n8 = nl & 7;
            w = ffn_w1[(n * 128 + kk) * 256 + dd];
        } else if (i < 649216) {                // ffn_w2 [7][256][128]
            int e = i - 419840;
            int n = e >> 15, r = e & 32767;
            int kk = r >> 7, dd = r & 127;
            base = F2B + n * 8192 + ((dd >> 6) * 2 + (kk >> 7)) * 2048; KTc = 8;
            int kl = kk & 127; kt = kl >> 4; kk16 = kk & 15;
            int nl = dd & 63; jt = nl >> 3; n8 = nl & 7;
            w = ffn_w2[(n * 256 + kk) * 128 + dd];
        } else if (i < 706560) {                // proj_w [7][128][64]
            int e = i - 649216;
            int n = e >> 13, r = e & 8191;
            int kk = r >> 6, dd = r & 63;
            base = PJB + n * 2048; KTc = 8;
            kt = kk >> 4; kk16 = kk & 15;
            jt = dd >> 3; n8 = dd & 7;
            w = proj_w[(n * 128 + kk) * 64 + dd];
        } else {                                // mix_w1 [448][128]
            int e = i - 706560;
            int kk = e >> 7, dd = e & 127;
            int kp = kk >> 7, ec = dd >> 6;
            KTc = (kp == 3) ? 4 : 8;
            base = MXB + ec * 7168 + kp * 2048;
            int kl = kk & 127; kt = kl >> 4; kk16 = kk & 15;
            int nl = dd & 63; jt = nl >> 3; n8 = nl & 7;
            w = mix_w1[kk * 128 + dd];
        }
        tq = (kk16 & 7) >> 1;
        int breg = kk16 >> 3, half = kk16 & 1;
        int slot = base + (jt * KTc + kt) * 32 + n8 * 4 + tq;
        unsigned short hb; asm("cvt.rn.bf16.f32 %0, %1;" : "=h"(hb) : "f"(w));
        float hf = __uint_as_float(((unsigned)hb) << 16);
        unsigned short lb; asm("cvt.rn.bf16.f32 %0, %1;" : "=h"(lb) : "f"(w - hf));
        wp[slot * 8 + breg * 2 + half] = hb;
        wp[slot * 8 + 4 + breg * 2 + half] = lb;
    }
}

#define STAGE_WAIT(hasnext) \
    if (hasnext) { asm volatile("cp.async.wait_group 1;" ::: "memory"); } \
    else         { asm volatile("cp.async.wait_group 0;" ::: "memory"); } \
    __syncthreads();

// ---------------- Kernel 1: per-band conv + LN + LN + FFN + proj ----------------
// smem (floats): HXP 0..2256 | HL 2256..10704 | ZP 10704..19408 | UP/FSC 19408..36304 | WB0 36304 | WB1 44496
#define K1F 52688
#define K1B (K1F * 4)

__global__ __launch_bounds__(NTHREADS, 1)
void band_kernel(const float* __restrict__ x,
                 const float* __restrict__ conv_b,
                 const float* __restrict__ dec_g, const float* __restrict__ dec_b,
                 const float* __restrict__ n2_g,  const float* __restrict__ n2_b,
                 const float* __restrict__ ffn_b1, const float* __restrict__ ffn_b2,
                 const float* __restrict__ proj_b)
{
    extern __shared__ float sm[];
    uint2* HXP = (uint2*)sm;                 // [94][12] pairs
    float* HL  = sm + 2256;                  // [64][132] f32
    uint2* ZP  = (uint2*)(sm + 10704);       // [64][68] pairs
    uint2* UP  = (uint2*)(sm + 19408);       // [64][132] pairs
    float* FSC = sm + 19408;                 // [64][136] f32 overlay (conv raw)
    uint4* WB0 = (uint4*)(sm + 36304);
    uint4* WB1 = (uint4*)(sm + 44496);

    const int tid = threadIdx.x, warp = tid >> 5, lane = tid & 31;
    const int n = blockIdx.z, b = blockIdx.y, t0 = blockIdx.x * TT;
    const int mb = (warp >> 1) << 4;         // 16-row tile base
    const int nh = warp & 1;                 // column half
    const int lg = lane >> 2, lt = lane & 3;
    const int mbg = mb + lg;

    const int taps = c_KS[n], off = c_off[n];
    const int ncc = (taps + 3) >> 2;
    const int NC = ncc + 9;
    int ci = 0;

    { int2 f0 = band_chunk(n, 0, ncc, taps); cp_chunk(WB0, g_wp + f0.x, f0.y); }

    // halo [t0-15, t0+78] x 16, split to bf16 pairs
    for (int pi = tid; pi < 94 * 8; pi += NTHREADS) {
        int it = pi >> 3, sp = pi & 7;
        int tt = t0 - 15 + it;
        float e0 = 0.f, e1 = 0.f;
        if (tt >= 0 && tt < TLEN) {
            float2 v = *(const float2*)&x[(b * TLEN + tt) * 16 + sp * 2];
            e0 = v.x; e1 = v.y;
        }
        HXP[it * 12 + sp] = split2(e0, e1);
    }

    // ---- conv: im2col GEMM, pipelined chunks of <=4 taps ----
    float4 D8[8];
    #pragma unroll
    for (int j = 0; j < 8; j++) D8[j] = make_float4(0.f, 0.f, 0.f, 0.f);
    for (int c = 0; c < ncc; c++) {
        const uint4* cur = (ci & 1) ? WB1 : WB0;
        if (ci + 1 < NC) {
            int2 nf = band_chunk(n, ci + 1, ncc, taps);
            cp_chunk(((ci + 1) & 1) ? WB1 : WB0, g_wp + nf.x, nf.y);
        }
        STAGE_WAIT(ci + 1 < NC);
        int KTc = min(4, taps - c * 4);
        const uint4* bp = cur + nh * 8 * KTc * 32 + lane;
        int rbase = mbg + off + c * 4;
        for (int kt = 0; kt < KTc; kt++) {
            const uint2* hp = HXP + (rbase + kt) * 12 + lt;
            uint2 P0 = hp[0], P2 = hp[4];
            uint2 P1 = hp[96], P3 = hp[100];         // +8 rows (8*12)
            #pragma unroll
            for (int j = 0; j < 8; j++) {
                uint4 Bv = bp[(j * KTc + kt) * 32];
                mma16(D8[j], P0.x, P1.x, P2.x, P3.x, Bv.x, Bv.y);
                mma16(D8[j], P0.x, P1.x, P2.x, P3.x, Bv.z, Bv.w);
                mma16(D8[j], P0.y, P1.y, P2.y, P3.y, Bv.x, Bv.y);
            }
        }
        __syncthreads(); ci++;
    }
    // store raw conv to f32 scratch for LN redistribution
    #pragma unroll
    for (int j = 0; j < 8; j++) {
        int col = nh * 64 + j * 8 + 2 * lt;
        *(float2*)&FSC[mbg * 136 + col]       = make_float2(D8[j].x, D8[j].y);
        *(float2*)&FSC[(mbg + 8) * 136 + col] = make_float2(D8[j].z, D8[j].w);
    }
    __syncthreads();

    // ---- bias + dec-LN + n2-LN (fp32 exact); write HL f32 + ZP pairs ----
    {
        float4 cb4 = *(const float4*)&conv_b[n * 128 + lane * 4];
        float4 g1  = *(const float4*)&dec_g [n * 128 + lane * 4];
        float4 bb1 = *(const float4*)&dec_b [n * 128 + lane * 4];
        float4 g2  = *(const float4*)&n2_g  [n * 128 + lane * 4];
        float4 bb2 = *(const float4*)&n2_b  [n * 128 + lane * 4];
        for (int tt = 0; tt < 8; tt++) {
            int row = warp * 8 + tt;
            float4 a = *(float4*)&FSC[row * 136 + lane * 4];
            a.x += cb4.x; a.y += cb4.y; a.z += cb4.z; a.w += cb4.w;
            float s1 = a.x + a.y + a.z + a.w;
            float s2 = fmaf(a.x, a.x, fmaf(a.y, a.y, fmaf(a.z, a.z, a.w * a.w)));
            #pragma unroll
            for (int o = 16; o; o >>= 1) {
                s1 += __shfl_xor_sync(0xffffffffu, s1, o);
                s2 += __shfl_xor_sync(0xffffffffu, s2, o);
            }
            float mean = s1 * 0.0078125f;
            float var  = s2 * 0.0078125f - mean * mean;
            float rs = rsqrtf(var + 1e-5f);
            float4 hl;
            hl.x = (a.x - mean) * rs * g1.x + bb1.x;
            hl.y = (a.y - mean) * rs * g1.y + bb1.y;
            hl.z = (a.z - mean) * rs * g1.z + bb1.z;
            hl.w = (a.w - mean) * rs * g1.w + bb1.w;
            float t1 = hl.x + hl.y + hl.z + hl.w;
            float t2 = fmaf(hl.x, hl.x, fmaf(hl.y, hl.y, fmaf(hl.z, hl.z, hl.w * hl.w)));
            #pragma unroll
            for (int o = 16; o; o >>= 1) {
                t1 += __shfl_xor_sync(0xffffffffu, t1, o);
                t2 += __shfl_xor_sync(0xffffffffu, t2, o);
            }
            float m2 = t1 * 0.0078125f;
            float v2 = t2 * 0.0078125f - m2 * m2;
            float rs2 = rsqrtf(v2 + 1e-5f);
            float4 z4;
            z4.x = (hl.x - m2) * rs2 * g2.x + bb2.x;
            z4.y = (hl.y - m2) * rs2 * g2.y + bb2.y;
            z4.z = (hl.z - m2) * rs2 * g2.z + bb2.z;
            z4.w = (hl.w - m2) * rs2 * g2.w + bb2.w;
            *(float4*)&HL[row * 132 + lane * 4] = hl;
            uint2 pA = split2(z4.x, z4.y), pB = split2(z4.z, z4.w);
            *(uint4*)&ZP[row * 68 + lane * 2] = make_uint4(pA.x, pA.y, pB.x, pB.y);
        }
    }

    // ---- FFN1: u = gelu(z @ W1 + b1), 4 chunks of 64 cols ----
    for (int ec = 0; ec < 4; ec++) {
        const uint4* cur = (ci & 1) ? WB1 : WB0;
        if (ci + 1 < NC) {
            int2 nf = band_chunk(n, ci + 1, ncc, taps);
            cp_chunk(((ci + 1) & 1) ? WB1 : WB0, g_wp + nf.x, nf.y);
        }
        STAGE_WAIT(ci + 1 < NC);
        int colb = ec * 64 + nh * 32;
        float4 Du[4];
        #pragma unroll
        for (int j = 0; j < 4; j++) {
            float2 bb = *(const float2*)&ffn_b1[n * 256 + colb + j * 8 + 2 * lt];
            Du[j] = make_float4(bb.x, bb.y, bb.x, bb.y);
        }
        wmma4<8>(ZP + mbg * 68 + lt, ZP + (mbg + 8) * 68 + lt, cur + nh * 1024 + lane, Du);
        #pragma unroll
        for (int j = 0; j < 4; j++) {
            int pc = ec * 32 + nh * 16 + j * 4 + lt;
            UP[mbg * 132 + pc]       = split2(gelu_exact(Du[j].x), gelu_exact(Du[j].y));
            UP[(mbg + 8) * 132 + pc] = split2(gelu_exact(Du[j].z), gelu_exact(Du[j].w));
        }
        __syncthreads(); ci++;
    }

    // ---- FFN2: band_out = h_ln + u @ W2 + b2 -> ZP pairs ----
    for (int ec2 = 0; ec2 < 2; ec2++) {
        int colb = ec2 * 64 + nh * 32;
        float4 Db[4];
        #pragma unroll
        for (int j = 0; j < 4; j++) {
            int col = colb + j * 8 + 2 * lt;
            float2 bb = *(const float2*)&ffn_b2[n * 128 + col];
            float2 h0 = *(float2*)&HL[mbg * 132 + col];
            float2 h1 = *(float2*)&HL[(mbg + 8) * 132 + col];
            Db[j] = make_float4(h0.x + bb.x, h0.y + bb.y, h1.x + bb.x, h1.y + bb.y);
        }
        for (int kp = 0; kp < 2; kp++) {
            const uint4* cur = (ci & 1) ? WB1 : WB0;
            if (ci + 1 < NC) {
                int2 nf = band_chunk(n, ci + 1, ncc, taps);
                cp_chunk(((ci + 1) & 1) ? WB1 : WB0, g_wp + nf.x, nf.y);
            }
            STAGE_WAIT(ci + 1 < NC);
            wmma4<8>(UP + mbg * 132 + kp * 64 + lt, UP + (mbg + 8) * 132 + kp * 64 + lt,
                     cur + nh * 1024 + lane, Db);
            __syncthreads(); ci++;
        }
        #pragma unroll
        for (int j = 0; j < 4; j++) {
            int pc = ec2 * 32 + nh * 16 + j * 4 + lt;
            ZP[mbg * 68 + pc]       = split2(Db[j].x, Db[j].y);
            ZP[(mbg + 8) * 68 + pc] = split2(Db[j].z, Db[j].w);
        }
    }

    // ---- proj -> g_cat (split pairs) ----
    {
        const uint4* cur = (ci & 1) ? WB1 : WB0;
        STAGE_WAIT(false);
        float4 Dp[4];
        #pragma unroll
        for (int j = 0; j < 4; j++) {
            float2 pb = *(const float2*)&proj_b[n * 64 + nh * 32 + j * 8 + 2 * lt];
            Dp[j] = make_float4(pb.x, pb.y, pb.x, pb.y);
        }
        wmma4<8>(ZP + mbg * 68 + lt, ZP + (mbg + 8) * 68 + lt, cur + nh * 1024 + lane, Dp);
        #pragma unroll
        for (int j = 0; j < 4; j++) {
            int pc = n * 32 + nh * 16 + j * 4 + lt;
            size_t r1 = (size_t)(b * TLEN + t0 + mbg) * 224;
            g_cat[r1 + pc]            = split2(Dp[j].x, Dp[j].y);
            g_cat[r1 + 8 * 224 + pc]  = split2(Dp[j].z, Dp[j].w);
        }
    }
}

// ---------------- Kernel 2: mix MLP ----------------
// smem (floats): CATP 0..29184 | M2 29184..37632 | WB0 37632 | WB1 45824 | W2 54016..56064
#define K2F 56064
#define K2B (K2F * 4)

__global__ __launch_bounds__(NTHREADS, 1)
void mix_kernel(const float* __restrict__ mix_b1, const float* __restrict__ mix_w2,
                const float* __restrict__ mix_b2, float* __restrict__ out)
{
    extern __shared__ float sm[];
    uint2* CATP = (uint2*)sm;                 // [64][228] pairs
    float* M2   = sm + 29184;                 // [64][132] f32
    uint4* WB0  = (uint4*)(sm + 37632);
    uint4* WB1  = (uint4*)(sm + 45824);
    float* W2   = sm + 54016;

    const int tid = threadIdx.x, warp = tid >> 5, lane = tid & 31;
    const int g0 = blockIdx.x * TT;
    const int mb = (warp >> 1) << 4;
    const int nh = warp & 1;
    const int lg = lane >> 2, lt = lane & 3;
    const int mbg = mb + lg;

    // cat copy (group 0): 64 rows x 112 u4 (FULL row), dst row stride 114 u4
    {
        const uint4* src = (const uint4*)(g_cat + (size_t)g0 * 224);
        unsigned sb = (unsigned)__cvta_generic_to_shared(CATP);
        for (int i = tid; i < 64 * 112; i += NTHREADS) {
            int r = i / 112, q = i - r * 112;
            asm volatile("cp.async.cg.shared.global [%0], [%1], 16;"
                         :: "r"(sb + (r * 114 + q) * 16), "l"(src + r * 112 + q));
        }
        asm volatile("cp.async.commit_group;" ::: "memory");
    }
    cp_chunk(WB0, g_wp + MXB, 2048);          // chunk 0

    float4 Dm[4];
    for (int idx = 0; idx < 8; idx++) {
        int ec = idx >> 2, kp = idx & 3;
        const uint4* cur = (idx & 1) ? WB1 : WB0;
        if (idx + 1 < 8) {
            int ec2 = (idx + 1) >> 2, kp2 = (idx + 1) & 3;
            cp_chunk(((idx + 1) & 1) ? WB1 : WB0,
                     g_wp + MXB + ec2 * 7168 + kp2 * 2048, (kp2 == 3) ? 1024 : 2048);
        }
        STAGE_WAIT(idx + 1 < 8);
        int colb = ec * 64 + nh * 32;
        if (kp == 0) {
            #pragma unroll
            for (int j = 0; j < 4; j++) {
                float2 bb = *(const float2*)&mix_b1[colb + j * 8 + 2 * lt];
                Dm[j] = make_float4(bb.x, bb.y, bb.x, bb.y);
            }
        }
        const uint2* A0 = CATP + mbg * 228 + kp * 64 + lt;
        const uint2* A1 = CATP + (mbg + 8) * 228 + kp * 64 + lt;
        if (kp < 3) wmma4<8>(A0, A1, cur + nh * 1024 + lane, Dm);
        else        wmma4<4>(A0, A1, cur + nh * 512  + lane, Dm);
        if (kp == 3) {
            #pragma unroll
            for (int j = 0; j < 4; j++) {
                int col = colb + j * 8 + 2 * lt;
                *(float2*)&M2[mbg * 132 + col] =
                    make_float2(gelu_exact(Dm[j].x), gelu_exact(Dm[j].y));
                *(float2*)&M2[(mbg + 8) * 132 + col] =
                    make_float2(gelu_exact(Dm[j].z), gelu_exact(Dm[j].w));
            }
        }
        __syncthreads();
    }
    for (int i4 = tid; i4 < 512; i4 += NTHREADS)
        *(float4*)&W2[i4 * 4] = *(const float4*)&mix_w2[i4 * 4];
    __syncthreads();

    // final 128->16 GEMM in exact fp32
    {
        const int tokBase = warp * 8;
        const int j = lane & 15, half = lane >> 4;
        float o[8];
        #pragma unroll
        for (int tt = 0; tt < 8; tt++) o[tt] = 0.f;
        for (int dd = 0; dd < 64; dd++) {
            int d = half * 64 + dd;
            float w = W2[d * 16 + j];
            #pragma unroll
            for (int tt = 0; tt < 8; tt++)
                o[tt] = fmaf(M2[(tokBase + tt) * 132 + d], w, o[tt]);
        }
        float bj = mix_b2[j];
        #pragma unroll
        for (int tt = 0; tt < 8; tt++) {
            o[tt] += __shfl_xor_sync(0xffffffffu, o[tt], 16);
            if (half == 0)
                out[(g0 + tokBase + tt) * 16 + j] = o[tt] + bj;
        }
    }
}

// ---------------- launch ----------------
extern "C" void kernel_launch(void* const* d_in, const int* in_sizes, int n_in,
                              void* d_out, int out_size)
{
    const float* x      = (const float*)d_in[0];
    const float* conv_w = (const float*)d_in[1];
    const float* conv_b = (const float*)d_in[2];
    const float* dec_g  = (const float*)d_in[3];
    const float* dec_b  = (const float*)d_in[4];
    const float* n2_g   = (const float*)d_in[5];
    const float* n2_b   = (const float*)d_in[6];
    const float* ffn_w1 = (const float*)d_in[7];
    const float* ffn_b1 = (const float*)d_in[8];
    const float* ffn_w2 = (const float*)d_in[9];
    const float* ffn_b2 = (const float*)d_in[10];
    const float* proj_w = (const float*)d_in[11];
    const float* proj_b = (const float*)d_in[12];
    const float* mix_w1 = (const float*)d_in[13];
    const float* mix_b1 = (const float*)d_in[14];
    const float* mix_w2 = (const float*)d_in[15];
    const float* mix_b2 = (const float*)d_in[16];
    float* out = (float*)d_out;

    cudaFuncSetAttribute(band_kernel, cudaFuncAttributeMaxDynamicSharedMemorySize, K1B);
    cudaFuncSetAttribute(mix_kernel,  cudaFuncAttributeMaxDynamicSharedMemorySize, K2B);

    pack_weights<<<1024, NTHREADS>>>(conv_w, ffn_w1, ffn_w2, proj_w, mix_w1);

    dim3 grid1(TLEN / TT, BATCH, NBANDS);
    band_kernel<<<grid1, NTHREADS, K1B>>>(x, conv_b, dec_g, dec_b, n2_g, n2_b,
                                          ffn_b1, ffn_b2, proj_b);
    mix_kernel<<<(BATCH * TLEN) / TT, NTHREADS, K2B>>>(mix_b1, mix_w2, mix_b2, out);
}